// round 3
// baseline (speedup 1.0000x reference)
#include <cuda_runtime.h>

// Problem constants (fixed by the dataset)
#define NN 50000
#define EE 1600000
#define HD 128

// -------- device scratch (no allocations allowed) --------
__device__ float g_x[(size_t)NN * HD];
__device__ float g_xw[(size_t)NN * HD];
__device__ float g_acc[(size_t)NN * HD];
__device__ float g_dis[NN];
__device__ int   g_cnt[NN];
__device__ int   g_src[EE];
__device__ int   g_dst[EE];
__device__ int   g_is64;

// ---------------------------------------------------------
// prep: detect edge dtype (int64 vs int32), convert, count in-degrees
// ---------------------------------------------------------
__global__ void detect_kernel(const int* __restrict__ ei32) {
    if (blockIdx.x == 0 && threadIdx.x == 0) {
        int orv = 0;
        #pragma unroll
        for (int i = 0; i < 16; i++) orv |= ei32[2 * i + 1];
        g_is64 = (orv == 0) ? 1 : 0;   // int64 little-endian high words are 0 (values < 50000)
    }
}

__global__ void zero_cnt_kernel(int n) {
    int i = blockIdx.x * blockDim.x + threadIdx.x;
    if (i < n) g_cnt[i] = 0;
}

__global__ void prep_edges_kernel(const void* __restrict__ eiv, int E) {
    int e = blockIdx.x * blockDim.x + threadIdx.x;
    if (e >= E) return;
    int s, d;
    if (g_is64) {
        const long long* ei = (const long long*)eiv;
        s = (int)ei[e];
        d = (int)ei[(size_t)E + e];
    } else {
        const int* ei = (const int*)eiv;
        s = ei[e];
        d = ei[E + e];
    }
    g_src[e] = s;
    g_dst[e] = d;
    atomicAdd(&g_cnt[d], 1);
}

__global__ void dis_kernel(int n) {
    int i = blockIdx.x * blockDim.x + threadIdx.x;
    if (i < n) g_dis[i] = rsqrtf((float)g_cnt[i] + 1.0f);  // +1 self-loop; deg>=1 always
}

// ---------------------------------------------------------
// SGEMM: C[M,128] = op(A[M,K]) @ B[K,128] + bias, optional relus
// BM=128, BN=128, BK=16, 256 threads, 8x8 per thread
// ---------------------------------------------------------
template <bool RELU_IN, bool RELU_OUT>
__global__ __launch_bounds__(256, 1) void sgemm_kernel(
    const float* __restrict__ A, const float* __restrict__ B,
    const float* __restrict__ bias, float* __restrict__ C, int M, int K)
{
    __shared__ float As[16][128];   // [k][m]
    __shared__ float Bs[16][128];   // [k][n]

    const int tid = threadIdx.x;
    const int m0  = blockIdx.x * 128;
    const int tx  = tid & 15;   // col group: cols tx*8 .. tx*8+7
    const int ty  = tid >> 4;   // row group: rows ty*8 .. ty*8+7

    float acc[8][8];
    #pragma unroll
    for (int i = 0; i < 8; i++)
        #pragma unroll
        for (int j = 0; j < 8; j++) acc[i][j] = 0.0f;

    for (int k0 = 0; k0 < K; k0 += 16) {
        // load A tile (128 rows x 16 k), transposed into As[k][m]
        #pragma unroll
        for (int i = 0; i < 2; i++) {
            int fi  = tid + i * 256;          // float4 index, 0..511
            int row = fi >> 2;                // 0..127
            int kq  = fi & 3;                 // 0..3 (float4 along k)
            float4 v = make_float4(0.f, 0.f, 0.f, 0.f);
            if (m0 + row < M)
                v = *(const float4*)(A + (size_t)(m0 + row) * K + k0 + kq * 4);
            if (RELU_IN) {
                v.x = fmaxf(v.x, 0.f); v.y = fmaxf(v.y, 0.f);
                v.z = fmaxf(v.z, 0.f); v.w = fmaxf(v.w, 0.f);
            }
            As[kq * 4 + 0][row] = v.x;
            As[kq * 4 + 1][row] = v.y;
            As[kq * 4 + 2][row] = v.z;
            As[kq * 4 + 3][row] = v.w;
        }
        // load B tile (16 k x 128 n)
        #pragma unroll
        for (int i = 0; i < 2; i++) {
            int fi  = tid + i * 256;
            int row = fi >> 5;                // 0..15
            int c4  = fi & 31;                // 0..31
            *(float4*)&Bs[row][c4 * 4] =
                *(const float4*)(B + (size_t)(k0 + row) * HD + c4 * 4);
        }
        __syncthreads();

        #pragma unroll
        for (int k = 0; k < 16; k++) {
            float4 a0 = *(const float4*)&As[k][ty * 8];
            float4 a1 = *(const float4*)&As[k][ty * 8 + 4];
            float4 b0 = *(const float4*)&Bs[k][tx * 8];
            float4 b1 = *(const float4*)&Bs[k][tx * 8 + 4];
            float av[8] = {a0.x, a0.y, a0.z, a0.w, a1.x, a1.y, a1.z, a1.w};
            float bv[8] = {b0.x, b0.y, b0.z, b0.w, b1.x, b1.y, b1.z, b1.w};
            #pragma unroll
            for (int i = 0; i < 8; i++)
                #pragma unroll
                for (int j = 0; j < 8; j++)
                    acc[i][j] = fmaf(av[i], bv[j], acc[i][j]);
        }
        __syncthreads();
    }

    float bvals[8];
    #pragma unroll
    for (int j = 0; j < 8; j++)
        bvals[j] = bias ? __ldg(&bias[tx * 8 + j]) : 0.0f;

    #pragma unroll
    for (int i = 0; i < 8; i++) {
        int m = m0 + ty * 8 + i;
        if (m < M) {
            float o[8];
            #pragma unroll
            for (int j = 0; j < 8; j++) {
                float v = acc[i][j] + bvals[j];
                if (RELU_OUT) v = fmaxf(v, 0.f);
                o[j] = v;
            }
            *(float4*)(C + (size_t)m * HD + tx * 8)     = make_float4(o[0], o[1], o[2], o[3]);
            *(float4*)(C + (size_t)m * HD + tx * 8 + 4) = make_float4(o[4], o[5], o[6], o[7]);
        }
    }
}

// ---------------------------------------------------------
// acc[i,h] = bias[h] + xw[i,h] * dis[i]^2   (self-loop + bias folded in)
// ---------------------------------------------------------
__global__ void init_acc_kernel(const float* __restrict__ xw,
                                const float* __restrict__ bias,
                                float* __restrict__ acc, int n)
{
    int idx = blockIdx.x * blockDim.x + threadIdx.x;   // float4 index
    if (idx >= n * 32) return;
    int i  = idx >> 5;
    int h4 = idx & 31;
    float ds = g_dis[i];
    float c  = ds * ds;
    float4 v = ((const float4*)xw)[idx];
    float4 b = ((const float4*)bias)[h4];
    ((float4*)acc)[idx] = make_float4(fmaf(v.x, c, b.x), fmaf(v.y, c, b.y),
                                      fmaf(v.z, c, b.z), fmaf(v.w, c, b.w));
}

// ---------------------------------------------------------
// edge scatter: acc[d] += xw[s] * dis[s]*dis[d]   (one warp per edge)
// ---------------------------------------------------------
__global__ void scatter_kernel(const float* __restrict__ xw,
                               float* __restrict__ acc, int E)
{
    int g    = blockIdx.x * blockDim.x + threadIdx.x;
    int w    = g >> 5;
    int lane = g & 31;
    if (w >= E) return;
    int s = g_src[w];
    int d = g_dst[w];
    float coef = g_dis[s] * g_dis[d];
    float4 v = *(const float4*)(xw + (size_t)s * HD + lane * 4);
    v.x *= coef; v.y *= coef; v.z *= coef; v.w *= coef;
    float* p = acc + (size_t)d * HD + lane * 4;
    asm volatile("red.global.add.v4.f32 [%0], {%1,%2,%3,%4};"
                 :: "l"(p), "f"(v.x), "f"(v.y), "f"(v.z), "f"(v.w)
                 : "memory");
}

// ---------------------------------------------------------
// edge score: sigmoid( relu(A[s]+B[d]) . w2 + b2 )   (one warp per edge)
// ---------------------------------------------------------
__global__ void edge_score_kernel(const float* __restrict__ Af,
                                  const float* __restrict__ Bf,
                                  const float* __restrict__ w2,
                                  const float* __restrict__ b2,
                                  float* __restrict__ out, int E)
{
    int g    = blockIdx.x * blockDim.x + threadIdx.x;
    int e    = g >> 5;
    int lane = g & 31;
    if (e >= E) return;
    int s = g_src[e];
    int d = g_dst[e];
    float4 a = *(const float4*)(Af + (size_t)s * HD + lane * 4);
    float4 b = *(const float4*)(Bf + (size_t)d * HD + lane * 4);
    float4 w = *(const float4*)(w2 + lane * 4);
    float sum = fmaxf(a.x + b.x, 0.f) * w.x
              + fmaxf(a.y + b.y, 0.f) * w.y
              + fmaxf(a.z + b.z, 0.f) * w.z
              + fmaxf(a.w + b.w, 0.f) * w.w;
    #pragma unroll
    for (int o = 16; o; o >>= 1) sum += __shfl_xor_sync(0xffffffffu, sum, o);
    if (lane == 0) {
        float z = sum + b2[0];
        out[e] = 1.0f / (1.0f + __expf(-z));
    }
}

// ---------------------------------------------------------
// host side
// ---------------------------------------------------------
static void gemm(const float* A, const float* B, const float* bias, float* C,
                 int M, int K, bool relu_in, bool relu_out)
{
    dim3 grid((M + 127) / 128);
    if (!relu_in && !relu_out)      sgemm_kernel<false, false><<<grid, 256>>>(A, B, bias, C, M, K);
    else if (!relu_in && relu_out)  sgemm_kernel<false, true ><<<grid, 256>>>(A, B, bias, C, M, K);
    else if (relu_in && !relu_out)  sgemm_kernel<true,  false><<<grid, 256>>>(A, B, bias, C, M, K);
    else                            sgemm_kernel<true,  true ><<<grid, 256>>>(A, B, bias, C, M, K);
}

extern "C" void kernel_launch(void* const* d_in, const int* in_sizes, int n_in,
                              void* d_out, int out_size)
{
    const float* nf      = (const float*)d_in[0];
    const void*  ei      = d_in[1];
    const float* enc_w1  = (const float*)d_in[2];
    const float* enc_b1  = (const float*)d_in[3];
    const float* enc_w2  = (const float*)d_in[4];
    const float* enc_b2  = (const float*)d_in[5];
    const float* conv_w[3] = {(const float*)d_in[6], (const float*)d_in[8], (const float*)d_in[10]};
    const float* conv_b[3] = {(const float*)d_in[7], (const float*)d_in[9], (const float*)d_in[11]};
    const float* cls_w1  = (const float*)d_in[12];
    const float* cls_b1  = (const float*)d_in[13];
    const float* cls_w2  = (const float*)d_in[14];
    const float* cls_b2  = (const float*)d_in[15];

    int K1 = in_sizes[2] / HD;        // encoder input dim (256)
    int N  = in_sizes[0] / K1;        // nodes
    int E  = in_sizes[1] / 2;         // edges

    float *px, *pxw, *pacc;
    cudaGetSymbolAddress((void**)&px,   g_x);
    cudaGetSymbolAddress((void**)&pxw,  g_xw);
    cudaGetSymbolAddress((void**)&pacc, g_acc);

    // prep
    detect_kernel<<<1, 32>>>((const int*)ei);
    zero_cnt_kernel<<<(N + 255) / 256, 256>>>(N);
    prep_edges_kernel<<<(E + 255) / 256, 256>>>(ei, E);
    dis_kernel<<<(N + 255) / 256, 256>>>(N);

    // node encoder: x = relu(nf@w1+b1) @ w2 + b2
    gemm(nf,  enc_w1, enc_b1, pxw, N, K1,  false, true);
    gemm(pxw, enc_w2, enc_b2, px,  N, HD,  false, false);

    // 3 GCN layers; relu of previous layer folded into GEMM A-load
    long ethreads = (long)E * 32;
    int  eblocks  = (int)((ethreads + 255) / 256);
    const float* cur = px;
    for (int l = 0; l < 3; l++) {
        gemm(cur, conv_w[l], nullptr, pxw, N, HD, l > 0, false);
        init_acc_kernel<<<(N * 32 + 255) / 256, 256>>>(pxw, conv_b[l], pacc, N);
        scatter_kernel<<<eblocks, 256>>>(pxw, pacc, E);
        cur = pacc;
    }

    // classifier factorization: A = x3@W1_top + b1, B = x3@W1_bot
    gemm(pacc, cls_w1,            cls_b1,  px,  N, HD, false, false);
    gemm(pacc, cls_w1 + HD * HD,  nullptr, pxw, N, HD, false, false);

    edge_score_kernel<<<eblocks, 256>>>(px, pxw, cls_w2, cls_b2, (float*)d_out, E);
}

// round 4
// speedup vs baseline: 2.0949x; 2.0949x over previous
#include <cuda_runtime.h>

// Problem constants (fixed by the dataset)
#define NN 50000
#define EE 1600000
#define HD 128

// -------- device scratch (no allocations allowed) --------
__device__ float g_x[(size_t)NN * HD];
__device__ float g_xw[(size_t)NN * HD];
__device__ float g_acc[(size_t)NN * HD];
__device__ float g_dis[NN];
__device__ int   g_cnt[NN];       // in-degree (no self loop)
__device__ int   g_rowstart[NN];  // CSR row start (by dst); scan scratch
__device__ int   g_woff[NN];      // running write offsets for fill
__device__ int   g_bsum[256];     // block sums for scan
__device__ int   g_boff[256];     // exclusive block offsets
__device__ int2  g_sd[EE];        // (src, dst) per original edge
__device__ int2  g_epack[EE];     // CSR payload: (src, coef bits)
__device__ int   g_is64;

// ---------------------------------------------------------
// prep: detect edge dtype (int64 vs int32)
// ---------------------------------------------------------
__global__ void detect_kernel(const int* __restrict__ ei32) {
    if (blockIdx.x == 0 && threadIdx.x == 0) {
        int orv = 0;
        #pragma unroll
        for (int i = 0; i < 16; i++) orv |= ei32[2 * i + 1];
        g_is64 = (orv == 0) ? 1 : 0;   // int64 high words are 0 (values < 50000)
    }
}

__global__ void zero_cnt_kernel(int n) {
    int i = blockIdx.x * blockDim.x + threadIdx.x;
    if (i < n) g_cnt[i] = 0;
}

__global__ void prep_edges_kernel(const void* __restrict__ eiv, int E) {
    int e = blockIdx.x * blockDim.x + threadIdx.x;
    if (e >= E) return;
    int s, d;
    if (g_is64) {
        const long long* ei = (const long long*)eiv;
        s = (int)ei[e];
        d = (int)ei[(size_t)E + e];
    } else {
        const int* ei = (const int*)eiv;
        s = ei[e];
        d = ei[E + e];
    }
    g_sd[e] = make_int2(s, d);
    atomicAdd(&g_cnt[d], 1);
}

__global__ void dis_kernel(int n) {
    int i = blockIdx.x * blockDim.x + threadIdx.x;
    if (i < n) g_dis[i] = rsqrtf((float)g_cnt[i] + 1.0f);  // +1 self-loop
}

// -------- 2-level exclusive scan of g_cnt -> g_rowstart, g_woff --------
__global__ void scan1_kernel(int n) {
    __shared__ int sh[256];
    int tx = threadIdx.x;
    int i  = blockIdx.x * 256 + tx;
    int v  = (i < n) ? g_cnt[i] : 0;
    sh[tx] = v;
    __syncthreads();
    #pragma unroll
    for (int o = 1; o < 256; o <<= 1) {
        int t = (tx >= o) ? sh[tx - o] : 0;
        __syncthreads();
        sh[tx] += t;
        __syncthreads();
    }
    if (i < n) g_rowstart[i] = sh[tx];            // inclusive within block
    if (tx == 255) g_bsum[blockIdx.x] = sh[255];
}

__global__ void scan2_kernel(int nb) {
    __shared__ int sh[256];
    int tx = threadIdx.x;
    int v  = (tx < nb) ? g_bsum[tx] : 0;
    sh[tx] = v;
    __syncthreads();
    #pragma unroll
    for (int o = 1; o < 256; o <<= 1) {
        int t = (tx >= o) ? sh[tx - o] : 0;
        __syncthreads();
        sh[tx] += t;
        __syncthreads();
    }
    if (tx < nb) g_boff[tx] = sh[tx] - v;         // exclusive
}

__global__ void scan3_kernel(int n) {
    int i = blockIdx.x * blockDim.x + threadIdx.x;
    if (i < n) {
        int start = g_rowstart[i] + g_boff[blockIdx.x] - g_cnt[i];  // exclusive prefix
        g_rowstart[i] = start;
        g_woff[i]     = start;
    }
}

__global__ void fill_kernel(int E) {
    int e = blockIdx.x * blockDim.x + threadIdx.x;
    if (e >= E) return;
    int2 sd = g_sd[e];
    int pos = atomicAdd(&g_woff[sd.y], 1);
    float coef = g_dis[sd.x] * g_dis[sd.y];
    g_epack[pos] = make_int2(sd.x, __float_as_int(coef));
}

// ---------------------------------------------------------
// SGEMM: C[M,128] = A[M,K] @ B[K,128] + bias, optional relus
// BM=128, BN=128, BK=16, 256 threads, 8x8 per thread
// ---------------------------------------------------------
template <bool RELU_IN, bool RELU_OUT>
__global__ __launch_bounds__(256, 2) void sgemm_kernel(
    const float* __restrict__ A, const float* __restrict__ B,
    const float* __restrict__ bias, float* __restrict__ C, int M, int K)
{
    __shared__ float As[16][128];   // [k][m]
    __shared__ float Bs[16][128];   // [k][n]

    const int tid = threadIdx.x;
    const int m0  = blockIdx.x * 128;
    const int tx  = tid & 15;
    const int ty  = tid >> 4;

    float acc[8][8];
    #pragma unroll
    for (int i = 0; i < 8; i++)
        #pragma unroll
        for (int j = 0; j < 8; j++) acc[i][j] = 0.0f;

    for (int k0 = 0; k0 < K; k0 += 16) {
        #pragma unroll
        for (int i = 0; i < 2; i++) {
            int fi  = tid + i * 256;
            int row = fi >> 2;
            int kq  = fi & 3;
            float4 v = make_float4(0.f, 0.f, 0.f, 0.f);
            if (m0 + row < M)
                v = *(const float4*)(A + (size_t)(m0 + row) * K + k0 + kq * 4);
            if (RELU_IN) {
                v.x = fmaxf(v.x, 0.f); v.y = fmaxf(v.y, 0.f);
                v.z = fmaxf(v.z, 0.f); v.w = fmaxf(v.w, 0.f);
            }
            As[kq * 4 + 0][row] = v.x;
            As[kq * 4 + 1][row] = v.y;
            As[kq * 4 + 2][row] = v.z;
            As[kq * 4 + 3][row] = v.w;
        }
        #pragma unroll
        for (int i = 0; i < 2; i++) {
            int fi  = tid + i * 256;
            int row = fi >> 5;
            int c4  = fi & 31;
            *(float4*)&Bs[row][c4 * 4] =
                *(const float4*)(B + (size_t)(k0 + row) * HD + c4 * 4);
        }
        __syncthreads();

        #pragma unroll
        for (int k = 0; k < 16; k++) {
            float4 a0 = *(const float4*)&As[k][ty * 8];
            float4 a1 = *(const float4*)&As[k][ty * 8 + 4];
            float4 b0 = *(const float4*)&Bs[k][tx * 8];
            float4 b1 = *(const float4*)&Bs[k][tx * 8 + 4];
            float av[8] = {a0.x, a0.y, a0.z, a0.w, a1.x, a1.y, a1.z, a1.w};
            float bv[8] = {b0.x, b0.y, b0.z, b0.w, b1.x, b1.y, b1.z, b1.w};
            #pragma unroll
            for (int i = 0; i < 8; i++)
                #pragma unroll
                for (int j = 0; j < 8; j++)
                    acc[i][j] = fmaf(av[i], bv[j], acc[i][j]);
        }
        __syncthreads();
    }

    float bvals[8];
    #pragma unroll
    for (int j = 0; j < 8; j++)
        bvals[j] = bias ? __ldg(&bias[tx * 8 + j]) : 0.0f;

    #pragma unroll
    for (int i = 0; i < 8; i++) {
        int m = m0 + ty * 8 + i;
        if (m < M) {
            float o[8];
            #pragma unroll
            for (int j = 0; j < 8; j++) {
                float v = acc[i][j] + bvals[j];
                if (RELU_OUT) v = fmaxf(v, 0.f);
                o[j] = v;
            }
            *(float4*)(C + (size_t)m * HD + tx * 8)     = make_float4(o[0], o[1], o[2], o[3]);
            *(float4*)(C + (size_t)m * HD + tx * 8 + 4) = make_float4(o[4], o[5], o[6], o[7]);
        }
    }
}

// ---------------------------------------------------------
// CSR aggregation: one warp per dst node, no atomics.
// out[i] = [relu]( bias + dis[i]^2 * xw[i] + sum_j coef_j * xw[src_j] )
// ---------------------------------------------------------
template <bool RELU>
__global__ void agg_kernel(const float* __restrict__ xw,
                           const float* __restrict__ bias,
                           float* __restrict__ out, int n)
{
    int g    = blockIdx.x * blockDim.x + threadIdx.x;
    int node = g >> 5;
    int lane = g & 31;
    if (node >= n) return;

    int start = g_rowstart[node];
    int deg   = g_cnt[node];
    float ds  = g_dis[node];
    float c   = ds * ds;

    float4 b = ((const float4*)bias)[lane];
    float4 v = *((const float4*)(xw + (size_t)node * HD) + lane);
    float4 acc = make_float4(fmaf(v.x, c, b.x), fmaf(v.y, c, b.y),
                             fmaf(v.z, c, b.z), fmaf(v.w, c, b.w));

    const int2* ep = g_epack + start;
    int j = 0;
    for (; j + 4 <= deg; j += 4) {
        int2 e0 = __ldg(ep + j);
        int2 e1 = __ldg(ep + j + 1);
        int2 e2 = __ldg(ep + j + 2);
        int2 e3 = __ldg(ep + j + 3);
        float4 u0 = *((const float4*)(xw + (size_t)e0.x * HD) + lane);
        float4 u1 = *((const float4*)(xw + (size_t)e1.x * HD) + lane);
        float4 u2 = *((const float4*)(xw + (size_t)e2.x * HD) + lane);
        float4 u3 = *((const float4*)(xw + (size_t)e3.x * HD) + lane);
        float w0 = __int_as_float(e0.y), w1 = __int_as_float(e1.y);
        float w2 = __int_as_float(e2.y), w3 = __int_as_float(e3.y);
        acc.x = fmaf(u0.x, w0, acc.x); acc.y = fmaf(u0.y, w0, acc.y);
        acc.z = fmaf(u0.z, w0, acc.z); acc.w = fmaf(u0.w, w0, acc.w);
        acc.x = fmaf(u1.x, w1, acc.x); acc.y = fmaf(u1.y, w1, acc.y);
        acc.z = fmaf(u1.z, w1, acc.z); acc.w = fmaf(u1.w, w1, acc.w);
        acc.x = fmaf(u2.x, w2, acc.x); acc.y = fmaf(u2.y, w2, acc.y);
        acc.z = fmaf(u2.z, w2, acc.z); acc.w = fmaf(u2.w, w2, acc.w);
        acc.x = fmaf(u3.x, w3, acc.x); acc.y = fmaf(u3.y, w3, acc.y);
        acc.z = fmaf(u3.z, w3, acc.z); acc.w = fmaf(u3.w, w3, acc.w);
    }
    for (; j < deg; j++) {
        int2 e0 = __ldg(ep + j);
        float4 u0 = *((const float4*)(xw + (size_t)e0.x * HD) + lane);
        float w0 = __int_as_float(e0.y);
        acc.x = fmaf(u0.x, w0, acc.x); acc.y = fmaf(u0.y, w0, acc.y);
        acc.z = fmaf(u0.z, w0, acc.z); acc.w = fmaf(u0.w, w0, acc.w);
    }

    if (RELU) {
        acc.x = fmaxf(acc.x, 0.f); acc.y = fmaxf(acc.y, 0.f);
        acc.z = fmaxf(acc.z, 0.f); acc.w = fmaxf(acc.w, 0.f);
    }
    *((float4*)(out + (size_t)node * HD) + lane) = acc;
}

// ---------------------------------------------------------
// edge score: sigmoid( relu(A[s]+B[d]) . w2 + b2 )   (one warp per edge)
// ---------------------------------------------------------
__global__ void edge_score_kernel(const float* __restrict__ Af,
                                  const float* __restrict__ Bf,
                                  const float* __restrict__ w2,
                                  const float* __restrict__ b2,
                                  float* __restrict__ out, int E)
{
    int g    = blockIdx.x * blockDim.x + threadIdx.x;
    int e    = g >> 5;
    int lane = g & 31;
    if (e >= E) return;
    int2 sd = g_sd[e];
    float4 a = *((const float4*)(Af + (size_t)sd.x * HD) + lane);
    float4 b = *((const float4*)(Bf + (size_t)sd.y * HD) + lane);
    float4 w = *((const float4*)w2 + lane);
    float sum = fmaxf(a.x + b.x, 0.f) * w.x
              + fmaxf(a.y + b.y, 0.f) * w.y
              + fmaxf(a.z + b.z, 0.f) * w.z
              + fmaxf(a.w + b.w, 0.f) * w.w;
    #pragma unroll
    for (int o = 16; o; o >>= 1) sum += __shfl_xor_sync(0xffffffffu, sum, o);
    if (lane == 0) {
        float z = sum + b2[0];
        out[e] = 1.0f / (1.0f + __expf(-z));
    }
}

// ---------------------------------------------------------
// host side
// ---------------------------------------------------------
static void gemm(const float* A, const float* B, const float* bias, float* C,
                 int M, int K, bool relu_in, bool relu_out)
{
    dim3 grid((M + 127) / 128);
    if (!relu_in && !relu_out)      sgemm_kernel<false, false><<<grid, 256>>>(A, B, bias, C, M, K);
    else if (!relu_in && relu_out)  sgemm_kernel<false, true ><<<grid, 256>>>(A, B, bias, C, M, K);
    else if (relu_in && !relu_out)  sgemm_kernel<true,  false><<<grid, 256>>>(A, B, bias, C, M, K);
    else                            sgemm_kernel<true,  true ><<<grid, 256>>>(A, B, bias, C, M, K);
}

extern "C" void kernel_launch(void* const* d_in, const int* in_sizes, int n_in,
                              void* d_out, int out_size)
{
    const float* nf      = (const float*)d_in[0];
    const void*  ei      = d_in[1];
    const float* enc_w1  = (const float*)d_in[2];
    const float* enc_b1  = (const float*)d_in[3];
    const float* enc_w2  = (const float*)d_in[4];
    const float* enc_b2  = (const float*)d_in[5];
    const float* conv_w[3] = {(const float*)d_in[6], (const float*)d_in[8], (const float*)d_in[10]};
    const float* conv_b[3] = {(const float*)d_in[7], (const float*)d_in[9], (const float*)d_in[11]};
    const float* cls_w1  = (const float*)d_in[12];
    const float* cls_b1  = (const float*)d_in[13];
    const float* cls_w2  = (const float*)d_in[14];
    const float* cls_b2  = (const float*)d_in[15];

    int K1 = in_sizes[2] / HD;        // encoder input dim (256)
    int N  = in_sizes[0] / K1;        // nodes
    int E  = in_sizes[1] / 2;         // edges

    float *px, *pxw, *pacc;
    cudaGetSymbolAddress((void**)&px,   g_x);
    cudaGetSymbolAddress((void**)&pxw,  g_xw);
    cudaGetSymbolAddress((void**)&pacc, g_acc);

    int nblk  = (N + 255) / 256;
    int eblk  = (E + 255) / 256;
    int wblk  = (int)(((long)N * 32 + 255) / 256);   // warp-per-node grids
    int ewblk = (int)(((long)E * 32 + 255) / 256);   // warp-per-edge grids

    // ---- prep: edge decode, degrees, CSR build ----
    detect_kernel<<<1, 32>>>((const int*)ei);
    zero_cnt_kernel<<<nblk, 256>>>(N);
    prep_edges_kernel<<<eblk, 256>>>(ei, E);
    dis_kernel<<<nblk, 256>>>(N);
    scan1_kernel<<<nblk, 256>>>(N);
    scan2_kernel<<<1, 256>>>(nblk);
    scan3_kernel<<<nblk, 256>>>(N);
    fill_kernel<<<eblk, 256>>>(E);

    // ---- node encoder: x = relu(nf@w1+b1) @ w2 + b2 ----
    gemm(nf,  enc_w1, enc_b1, pxw, N, K1, false, true);
    gemm(pxw, enc_w2, enc_b2, px,  N, HD, false, false);

    // ---- 3 GCN layers: GEMM then CSR aggregate (bias+self+relu fused) ----
    const float* cur = px;
    for (int l = 0; l < 3; l++) {
        gemm(cur, conv_w[l], nullptr, pxw, N, HD, false, false);
        if (l < 2) agg_kernel<true ><<<wblk, 256>>>(pxw, conv_b[l], pacc, N);
        else       agg_kernel<false><<<wblk, 256>>>(pxw, conv_b[l], pacc, N);
        cur = pacc;
    }

    // ---- classifier factorization: A = x3@W1_top + b1, B = x3@W1_bot ----
    gemm(pacc, cls_w1,           cls_b1,  px,  N, HD, false, false);
    gemm(pacc, cls_w1 + HD * HD, nullptr, pxw, N, HD, false, false);

    edge_score_kernel<<<ewblk, 256>>>(px, pxw, cls_w2, cls_b2, (float*)d_out, E);
}

// round 5
// speedup vs baseline: 3.1884x; 1.5220x over previous
#include <cuda_runtime.h>
#include <cstdint>

// Problem constants (fixed by the dataset)
#define NN 50000
#define EE 1600000
#define HD 128

// -------- device scratch (no allocations allowed) --------
__device__ float g_x[(size_t)NN * HD];
__device__ float g_xw[(size_t)NN * HD];
__device__ float g_acc[(size_t)NN * HD];
__device__ float g_dis[NN];
__device__ int   g_cnt[NN];       // in-degree (no self loop)
__device__ int   g_rowstart[NN];  // CSR row start (by dst)
__device__ int   g_woff[NN];      // running write offsets for fill
__device__ int   g_bsum[256];     // block sums for scan
__device__ int   g_boff[256];     // exclusive block offsets
__device__ int2  g_sd[EE];        // (src, dst) per original edge
__device__ int2  g_epack[EE];     // CSR payload: (src, coef bits)
__device__ int   g_is64;

// ---------------------------------------------------------
// prep: detect edge dtype (int64 vs int32)
// ---------------------------------------------------------
__global__ void detect_kernel(const int* __restrict__ ei32) {
    if (blockIdx.x == 0 && threadIdx.x == 0) {
        int orv = 0;
        #pragma unroll
        for (int i = 0; i < 16; i++) orv |= ei32[2 * i + 1];
        g_is64 = (orv == 0) ? 1 : 0;   // int64 high words are 0 (values < 50000)
    }
}

__global__ void zero_cnt_kernel(int n) {
    int i = blockIdx.x * blockDim.x + threadIdx.x;
    if (i < n) g_cnt[i] = 0;
}

__global__ void prep_edges_kernel(const void* __restrict__ eiv, int E) {
    int e = blockIdx.x * blockDim.x + threadIdx.x;
    if (e >= E) return;
    int s, d;
    if (g_is64) {
        const long long* ei = (const long long*)eiv;
        s = (int)ei[e];
        d = (int)ei[(size_t)E + e];
    } else {
        const int* ei = (const int*)eiv;
        s = ei[e];
        d = ei[E + e];
    }
    g_sd[e] = make_int2(s, d);
    atomicAdd(&g_cnt[d], 1);
}

__global__ void dis_kernel(int n) {
    int i = blockIdx.x * blockDim.x + threadIdx.x;
    if (i < n) g_dis[i] = rsqrtf((float)g_cnt[i] + 1.0f);  // +1 self-loop
}

// -------- 2-level exclusive scan of g_cnt -> g_rowstart, g_woff --------
__global__ void scan1_kernel(int n) {
    __shared__ int sh[256];
    int tx = threadIdx.x;
    int i  = blockIdx.x * 256 + tx;
    int v  = (i < n) ? g_cnt[i] : 0;
    sh[tx] = v;
    __syncthreads();
    #pragma unroll
    for (int o = 1; o < 256; o <<= 1) {
        int t = (tx >= o) ? sh[tx - o] : 0;
        __syncthreads();
        sh[tx] += t;
        __syncthreads();
    }
    if (i < n) g_rowstart[i] = sh[tx];
    if (tx == 255) g_bsum[blockIdx.x] = sh[255];
}

__global__ void scan2_kernel(int nb) {
    __shared__ int sh[256];
    int tx = threadIdx.x;
    int v  = (tx < nb) ? g_bsum[tx] : 0;
    sh[tx] = v;
    __syncthreads();
    #pragma unroll
    for (int o = 1; o < 256; o <<= 1) {
        int t = (tx >= o) ? sh[tx - o] : 0;
        __syncthreads();
        sh[tx] += t;
        __syncthreads();
    }
    if (tx < nb) g_boff[tx] = sh[tx] - v;
}

__global__ void scan3_kernel(int n) {
    int i = blockIdx.x * blockDim.x + threadIdx.x;
    if (i < n) {
        int start = g_rowstart[i] + g_boff[blockIdx.x] - g_cnt[i];
        g_rowstart[i] = start;
        g_woff[i]     = start;
    }
}

__global__ void fill_kernel(int E) {
    int e = blockIdx.x * blockDim.x + threadIdx.x;
    if (e >= E) return;
    int2 sd = g_sd[e];
    int pos = atomicAdd(&g_woff[sd.y], 1);
    float coef = g_dis[sd.x] * g_dis[sd.y];
    g_epack[pos] = make_int2(sd.x, __float_as_int(coef));
}

// ---------------------------------------------------------
// TF32 tensor-core GEMM: C[M,128] = A[M,K] @ B[K,128] + bias [,relu]
// BM=128, BN=128, BK=32, 256 threads (8 warps, 4x2), warp tile 32x64
// mma.sync.aligned.m16n8k8.tf32
// ---------------------------------------------------------
__device__ __forceinline__ uint32_t f2tf32(float f) {
    uint32_t r;
    asm("cvt.rna.tf32.f32 %0, %1;" : "=r"(r) : "f"(f));
    return r;
}

__device__ __forceinline__ void mma_tf32(float c[4],
                                         uint32_t a0, uint32_t a1, uint32_t a2, uint32_t a3,
                                         uint32_t b0, uint32_t b1) {
    asm volatile(
        "mma.sync.aligned.m16n8k8.row.col.f32.tf32.tf32.f32 "
        "{%0,%1,%2,%3}, {%4,%5,%6,%7}, {%8,%9}, {%0,%1,%2,%3};"
        : "+f"(c[0]), "+f"(c[1]), "+f"(c[2]), "+f"(c[3])
        : "r"(a0), "r"(a1), "r"(a2), "r"(a3), "r"(b0), "r"(b1));
}

#define AS_STRIDE 36   // BK(32)+4 pad  -> conflict-free A frag loads
#define BS_STRIDE 136  // BN(128)+8 pad -> conflict-free B frag loads

template <bool RELU_OUT>
__global__ __launch_bounds__(256, 2) void tgemm_kernel(
    const float* __restrict__ A, const float* __restrict__ B,
    const float* __restrict__ bias, float* __restrict__ C, int M, int K)
{
    __shared__ uint32_t As[128 * AS_STRIDE];  // [m][k] tf32 bits
    __shared__ uint32_t Bs[32 * BS_STRIDE];   // [k][n] tf32 bits

    const int tid    = threadIdx.x;
    const int wid    = tid >> 5;
    const int lane   = tid & 31;
    const int gid    = lane >> 2;   // group id (0..7)
    const int tig    = lane & 3;    // thread in group (0..3)
    const int warp_m = wid >> 1;    // 0..3  -> rows warp_m*32
    const int warp_n = wid & 1;     // 0..1  -> cols warp_n*64
    const int m0     = blockIdx.x * 128;

    float acc[2][8][4];
    #pragma unroll
    for (int mt = 0; mt < 2; mt++)
        #pragma unroll
        for (int nt = 0; nt < 8; nt++)
            #pragma unroll
            for (int i = 0; i < 4; i++) acc[mt][nt][i] = 0.0f;

    for (int k0 = 0; k0 < K; k0 += 32) {
        // ---- load A tile: 128 rows x 32 k, row-major w/ pad, cvt to tf32 ----
        #pragma unroll
        for (int i = 0; i < 4; i++) {
            int fi  = tid + i * 256;       // float4 index 0..1023
            int row = fi >> 3;             // 0..127
            int c4  = fi & 7;              // 0..7
            float4 v = make_float4(0.f, 0.f, 0.f, 0.f);
            if (m0 + row < M)
                v = *(const float4*)(A + (size_t)(m0 + row) * K + k0 + c4 * 4);
            uint32_t* p = &As[row * AS_STRIDE + c4 * 4];
            p[0] = f2tf32(v.x); p[1] = f2tf32(v.y);
            p[2] = f2tf32(v.z); p[3] = f2tf32(v.w);
        }
        // ---- load B tile: 32 k x 128 n ----
        #pragma unroll
        for (int i = 0; i < 4; i++) {
            int fi  = tid + i * 256;
            int row = fi >> 5;             // 0..31
            int c4  = fi & 31;             // 0..31
            float4 v = *(const float4*)(B + (size_t)(k0 + row) * HD + c4 * 4);
            uint32_t* p = &Bs[row * BS_STRIDE + c4 * 4];
            p[0] = f2tf32(v.x); p[1] = f2tf32(v.y);
            p[2] = f2tf32(v.z); p[3] = f2tf32(v.w);
        }
        __syncthreads();

        #pragma unroll
        for (int kk = 0; kk < 32; kk += 8) {
            // A fragments: 2 m-tiles x 4 regs
            uint32_t af[2][4];
            #pragma unroll
            for (int mt = 0; mt < 2; mt++) {
                int rbase = warp_m * 32 + mt * 16;
                af[mt][0] = As[(rbase + gid)     * AS_STRIDE + kk + tig];
                af[mt][1] = As[(rbase + gid + 8) * AS_STRIDE + kk + tig];
                af[mt][2] = As[(rbase + gid)     * AS_STRIDE + kk + tig + 4];
                af[mt][3] = As[(rbase + gid + 8) * AS_STRIDE + kk + tig + 4];
            }
            // B fragments: 8 n-tiles x 2 regs
            uint32_t bf[8][2];
            #pragma unroll
            for (int nt = 0; nt < 8; nt++) {
                int nbase = warp_n * 64 + nt * 8;
                bf[nt][0] = Bs[(kk + tig)     * BS_STRIDE + nbase + gid];
                bf[nt][1] = Bs[(kk + tig + 4) * BS_STRIDE + nbase + gid];
            }
            #pragma unroll
            for (int mt = 0; mt < 2; mt++)
                #pragma unroll
                for (int nt = 0; nt < 8; nt++)
                    mma_tf32(acc[mt][nt], af[mt][0], af[mt][1], af[mt][2], af[mt][3],
                             bf[nt][0], bf[nt][1]);
        }
        __syncthreads();
    }

    // ---- epilogue: bias + optional relu, float2 stores ----
    #pragma unroll
    for (int mt = 0; mt < 2; mt++) {
        #pragma unroll
        for (int half = 0; half < 2; half++) {
            int m = m0 + warp_m * 32 + mt * 16 + gid + half * 8;
            if (m < M) {
                #pragma unroll
                for (int nt = 0; nt < 8; nt++) {
                    int col = warp_n * 64 + nt * 8 + tig * 2;
                    float v0 = acc[mt][nt][half * 2 + 0];
                    float v1 = acc[mt][nt][half * 2 + 1];
                    if (bias) {
                        v0 += __ldg(&bias[col]);
                        v1 += __ldg(&bias[col + 1]);
                    }
                    if (RELU_OUT) { v0 = fmaxf(v0, 0.f); v1 = fmaxf(v1, 0.f); }
                    *(float2*)(C + (size_t)m * HD + col) = make_float2(v0, v1);
                }
            }
        }
    }
}

// ---------------------------------------------------------
// CSR aggregation: one warp per dst node, no atomics.
// out[i] = [relu]( bias + dis[i]^2 * xw[i] + sum_j coef_j * xw[src_j] )
// ---------------------------------------------------------
template <bool RELU>
__global__ void agg_kernel(const float* __restrict__ xw,
                           const float* __restrict__ bias,
                           float* __restrict__ out, int n)
{
    int g    = blockIdx.x * blockDim.x + threadIdx.x;
    int node = g >> 5;
    int lane = g & 31;
    if (node >= n) return;

    int start = g_rowstart[node];
    int deg   = g_cnt[node];
    float ds  = g_dis[node];
    float c   = ds * ds;

    float4 b = ((const float4*)bias)[lane];
    float4 v = *((const float4*)(xw + (size_t)node * HD) + lane);
    float4 acc = make_float4(fmaf(v.x, c, b.x), fmaf(v.y, c, b.y),
                             fmaf(v.z, c, b.z), fmaf(v.w, c, b.w));

    const int2* ep = g_epack + start;
    int j = 0;
    for (; j + 4 <= deg; j += 4) {
        int2 e0 = __ldg(ep + j);
        int2 e1 = __ldg(ep + j + 1);
        int2 e2 = __ldg(ep + j + 2);
        int2 e3 = __ldg(ep + j + 3);
        float4 u0 = *((const float4*)(xw + (size_t)e0.x * HD) + lane);
        float4 u1 = *((const float4*)(xw + (size_t)e1.x * HD) + lane);
        float4 u2 = *((const float4*)(xw + (size_t)e2.x * HD) + lane);
        float4 u3 = *((const float4*)(xw + (size_t)e3.x * HD) + lane);
        float w0 = __int_as_float(e0.y), w1 = __int_as_float(e1.y);
        float w2 = __int_as_float(e2.y), w3 = __int_as_float(e3.y);
        acc.x = fmaf(u0.x, w0, acc.x); acc.y = fmaf(u0.y, w0, acc.y);
        acc.z = fmaf(u0.z, w0, acc.z); acc.w = fmaf(u0.w, w0, acc.w);
        acc.x = fmaf(u1.x, w1, acc.x); acc.y = fmaf(u1.y, w1, acc.y);
        acc.z = fmaf(u1.z, w1, acc.z); acc.w = fmaf(u1.w, w1, acc.w);
        acc.x = fmaf(u2.x, w2, acc.x); acc.y = fmaf(u2.y, w2, acc.y);
        acc.z = fmaf(u2.z, w2, acc.z); acc.w = fmaf(u2.w, w2, acc.w);
        acc.x = fmaf(u3.x, w3, acc.x); acc.y = fmaf(u3.y, w3, acc.y);
        acc.z = fmaf(u3.z, w3, acc.z); acc.w = fmaf(u3.w, w3, acc.w);
    }
    for (; j < deg; j++) {
        int2 e0 = __ldg(ep + j);
        float4 u0 = *((const float4*)(xw + (size_t)e0.x * HD) + lane);
        float w0 = __int_as_float(e0.y);
        acc.x = fmaf(u0.x, w0, acc.x); acc.y = fmaf(u0.y, w0, acc.y);
        acc.z = fmaf(u0.z, w0, acc.z); acc.w = fmaf(u0.w, w0, acc.w);
    }

    if (RELU) {
        acc.x = fmaxf(acc.x, 0.f); acc.y = fmaxf(acc.y, 0.f);
        acc.z = fmaxf(acc.z, 0.f); acc.w = fmaxf(acc.w, 0.f);
    }
    *((float4*)(out + (size_t)node * HD) + lane) = acc;
}

// ---------------------------------------------------------
// edge score: sigmoid( relu(A[s]+B[d]) . w2 + b2 )   (one warp per edge)
// ---------------------------------------------------------
__global__ void edge_score_kernel(const float* __restrict__ Af,
                                  const float* __restrict__ Bf,
                                  const float* __restrict__ w2,
                                  const float* __restrict__ b2,
                                  float* __restrict__ out, int E)
{
    int g    = blockIdx.x * blockDim.x + threadIdx.x;
    int e    = g >> 5;
    int lane = g & 31;
    if (e >= E) return;
    int2 sd = g_sd[e];
    float4 a = *((const float4*)(Af + (size_t)sd.x * HD) + lane);
    float4 b = *((const float4*)(Bf + (size_t)sd.y * HD) + lane);
    float4 w = *((const float4*)w2 + lane);
    float sum = fmaxf(a.x + b.x, 0.f) * w.x
              + fmaxf(a.y + b.y, 0.f) * w.y
              + fmaxf(a.z + b.z, 0.f) * w.z
              + fmaxf(a.w + b.w, 0.f) * w.w;
    #pragma unroll
    for (int o = 16; o; o >>= 1) sum += __shfl_xor_sync(0xffffffffu, sum, o);
    if (lane == 0) {
        float z = sum + b2[0];
        out[e] = 1.0f / (1.0f + __expf(-z));
    }
}

// ---------------------------------------------------------
// host side
// ---------------------------------------------------------
static void gemm(const float* A, const float* B, const float* bias, float* C,
                 int M, int K, bool relu_out)
{
    dim3 grid((M + 127) / 128);
    if (relu_out) tgemm_kernel<true ><<<grid, 256>>>(A, B, bias, C, M, K);
    else          tgemm_kernel<false><<<grid, 256>>>(A, B, bias, C, M, K);
}

extern "C" void kernel_launch(void* const* d_in, const int* in_sizes, int n_in,
                              void* d_out, int out_size)
{
    const float* nf      = (const float*)d_in[0];
    const void*  ei      = d_in[1];
    const float* enc_w1  = (const float*)d_in[2];
    const float* enc_b1  = (const float*)d_in[3];
    const float* enc_w2  = (const float*)d_in[4];
    const float* enc_b2  = (const float*)d_in[5];
    const float* conv_w[3] = {(const float*)d_in[6], (const float*)d_in[8], (const float*)d_in[10]};
    const float* conv_b[3] = {(const float*)d_in[7], (const float*)d_in[9], (const float*)d_in[11]};
    const float* cls_w1  = (const float*)d_in[12];
    const float* cls_b1  = (const float*)d_in[13];
    const float* cls_w2  = (const float*)d_in[14];
    const float* cls_b2  = (const float*)d_in[15];

    int K1 = in_sizes[2] / HD;        // encoder input dim (256)
    int N  = in_sizes[0] / K1;        // nodes
    int E  = in_sizes[1] / 2;         // edges

    float *px, *pxw, *pacc;
    cudaGetSymbolAddress((void**)&px,   g_x);
    cudaGetSymbolAddress((void**)&pxw,  g_xw);
    cudaGetSymbolAddress((void**)&pacc, g_acc);

    int nblk  = (N + 255) / 256;
    int eblk  = (E + 255) / 256;
    int wblk  = (int)(((long)N * 32 + 255) / 256);   // warp-per-node grids
    int ewblk = (int)(((long)E * 32 + 255) / 256);   // warp-per-edge grids

    // ---- prep: edge decode, degrees, CSR build ----
    detect_kernel<<<1, 32>>>((const int*)ei);
    zero_cnt_kernel<<<nblk, 256>>>(N);
    prep_edges_kernel<<<eblk, 256>>>(ei, E);
    dis_kernel<<<nblk, 256>>>(N);
    scan1_kernel<<<nblk, 256>>>(N);
    scan2_kernel<<<1, 256>>>(nblk);
    scan3_kernel<<<nblk, 256>>>(N);
    fill_kernel<<<eblk, 256>>>(E);

    // ---- node encoder: x = relu(nf@w1+b1) @ w2 + b2 ----
    gemm(nf,  enc_w1, enc_b1, pxw, N, K1, true);
    gemm(pxw, enc_w2, enc_b2, px,  N, HD, false);

    // ---- 3 GCN layers: GEMM then CSR aggregate (bias+self+relu fused) ----
    const float* cur = px;
    for (int l = 0; l < 3; l++) {
        gemm(cur, conv_w[l], nullptr, pxw, N, HD, false);
        if (l < 2) agg_kernel<true ><<<wblk, 256>>>(pxw, conv_b[l], pacc, N);
        else       agg_kernel<false><<<wblk, 256>>>(pxw, conv_b[l], pacc, N);
        cur = pacc;
    }

    // ---- classifier factorization: A = x3@W1_top + b1, B = x3@W1_bot ----
    gemm(pacc, cls_w1,           cls_b1,  px,  N, HD, false);
    gemm(pacc, cls_w1 + HD * HD, nullptr, pxw, N, HD, false);

    edge_score_kernel<<<ewblk, 256>>>(px, pxw, cls_w2, cls_b2, (float*)d_out, E);
}

// round 7
// speedup vs baseline: 3.4783x; 1.0909x over previous
#include <cuda_runtime.h>
#include <cuda_bf16.h>
#include <cstdint>

// Problem constants (fixed by the dataset)
#define NN 50000
#define EE 1600000
#define HD 128

// -------- device scratch (no allocations allowed) --------
__device__ float g_x[(size_t)NN * HD];       // fp32 node feats (encoder out / scratch)
__device__ float g_xw[(size_t)NN * HD];      // fp32 scratch (encoder mid)
__device__ float g_acc[(size_t)NN * HD];     // fp32 agg output
__device__ __nv_bfloat162 g_bf1[(size_t)NN * 64];  // bf16 gather arrays
__device__ __nv_bfloat162 g_bf2[(size_t)NN * 64];
__device__ float g_dis[NN];
__device__ int   g_cnt[NN];       // in-degree (no self loop)
__device__ int   g_rowstart[NN];  // CSR row start (by dst)
__device__ int   g_woff[NN];      // running write offsets for fill
__device__ int   g_bsum[256];     // block sums for scan
__device__ int   g_boff[256];     // exclusive block offsets
__device__ int2  g_sd[EE];        // (src, dst) per original edge
__device__ int2  g_epack[EE];     // CSR payload: (src, coef bits)
__device__ int   g_is64;

// ---------------------------------------------------------
// prep: detect edge dtype (int64 vs int32)
// ---------------------------------------------------------
__global__ void detect_kernel(const int* __restrict__ ei32) {
    if (blockIdx.x == 0 && threadIdx.x == 0) {
        int orv = 0;
        #pragma unroll
        for (int i = 0; i < 16; i++) orv |= ei32[2 * i + 1];
        g_is64 = (orv == 0) ? 1 : 0;   // int64 high words are 0 (values < 50000)
    }
}

__global__ void zero_cnt_kernel(int n) {
    int i = blockIdx.x * blockDim.x + threadIdx.x;
    if (i < n) g_cnt[i] = 0;
}

__global__ void prep_edges_kernel(const void* __restrict__ eiv, int E) {
    int e = blockIdx.x * blockDim.x + threadIdx.x;
    if (e >= E) return;
    int s, d;
    if (g_is64) {
        const long long* ei = (const long long*)eiv;
        s = (int)ei[e];
        d = (int)ei[(size_t)E + e];
    } else {
        const int* ei = (const int*)eiv;
        s = ei[e];
        d = ei[E + e];
    }
    g_sd[e] = make_int2(s, d);
    atomicAdd(&g_cnt[d], 1);
}

__global__ void dis_kernel(int n) {
    int i = blockIdx.x * blockDim.x + threadIdx.x;
    if (i < n) g_dis[i] = rsqrtf((float)g_cnt[i] + 1.0f);  // +1 self-loop
}

// -------- 2-level exclusive scan of g_cnt -> g_rowstart, g_woff --------
__global__ void scan1_kernel(int n) {
    __shared__ int sh[256];
    int tx = threadIdx.x;
    int i  = blockIdx.x * 256 + tx;
    int v  = (i < n) ? g_cnt[i] : 0;
    sh[tx] = v;
    __syncthreads();
    #pragma unroll
    for (int o = 1; o < 256; o <<= 1) {
        int t = (tx >= o) ? sh[tx - o] : 0;
        __syncthreads();
        sh[tx] += t;
        __syncthreads();
    }
    if (i < n) g_rowstart[i] = sh[tx];
    if (tx == 255) g_bsum[blockIdx.x] = sh[255];
}

__global__ void scan2_kernel(int nb) {
    __shared__ int sh[256];
    int tx = threadIdx.x;
    int v  = (tx < nb) ? g_bsum[tx] : 0;
    sh[tx] = v;
    __syncthreads();
    #pragma unroll
    for (int o = 1; o < 256; o <<= 1) {
        int t = (tx >= o) ? sh[tx - o] : 0;
        __syncthreads();
        sh[tx] += t;
        __syncthreads();
    }
    if (tx < nb) g_boff[tx] = sh[tx] - v;
}

__global__ void scan3_kernel(int n) {
    int i = blockIdx.x * blockDim.x + threadIdx.x;
    if (i < n) {
        int start = g_rowstart[i] + g_boff[blockIdx.x] - g_cnt[i];
        g_rowstart[i] = start;
        g_woff[i]     = start;
    }
}

__global__ void fill_kernel(int E) {
    int e = blockIdx.x * blockDim.x + threadIdx.x;
    if (e >= E) return;
    int2 sd = g_sd[e];
    int pos = atomicAdd(&g_woff[sd.y], 1);
    float coef = g_dis[sd.x] * g_dis[sd.y];
    g_epack[pos] = make_int2(sd.x, __float_as_int(coef));
}

// ---------------------------------------------------------
// TF32 tensor-core GEMM: C[M,128] = A[M,K] @ B[K,128] + bias [,relu]
// BM=128, BN=128, BK=32, 256 threads (8 warps, 4x2), warp tile 32x64
// Output either fp32 (C) or bf16 (Cbf, row = 64 x __nv_bfloat162)
// ---------------------------------------------------------
__device__ __forceinline__ uint32_t f2tf32(float f) {
    uint32_t r;
    asm("cvt.rna.tf32.f32 %0, %1;" : "=r"(r) : "f"(f));
    return r;
}

__device__ __forceinline__ void mma_tf32(float c[4],
                                         uint32_t a0, uint32_t a1, uint32_t a2, uint32_t a3,
                                         uint32_t b0, uint32_t b1) {
    asm volatile(
        "mma.sync.aligned.m16n8k8.row.col.f32.tf32.tf32.f32 "
        "{%0,%1,%2,%3}, {%4,%5,%6,%7}, {%8,%9}, {%0,%1,%2,%3};"
        : "+f"(c[0]), "+f"(c[1]), "+f"(c[2]), "+f"(c[3])
        : "r"(a0), "r"(a1), "r"(a2), "r"(a3), "r"(b0), "r"(b1));
}

#define AS_STRIDE 36   // BK(32)+4 pad  -> conflict-free A frag loads
#define BS_STRIDE 136  // BN(128)+8 pad -> conflict-free B frag loads

template <bool RELU_OUT, bool BF16_OUT>
__global__ __launch_bounds__(256, 2) void tgemm_kernel(
    const float* __restrict__ A, const float* __restrict__ B,
    const float* __restrict__ bias, float* __restrict__ C,
    __nv_bfloat162* __restrict__ Cbf, int M, int K)
{
    __shared__ uint32_t As[128 * AS_STRIDE];  // [m][k] tf32 bits
    __shared__ uint32_t Bs[32 * BS_STRIDE];   // [k][n] tf32 bits

    const int tid    = threadIdx.x;
    const int wid    = tid >> 5;
    const int lane   = tid & 31;
    const int gid    = lane >> 2;   // group id (0..7)
    const int tig    = lane & 3;    // thread in group (0..3)
    const int warp_m = wid >> 1;    // 0..3  -> rows warp_m*32
    const int warp_n = wid & 1;     // 0..1  -> cols warp_n*64
    const int m0     = blockIdx.x * 128;

    float acc[2][8][4];
    #pragma unroll
    for (int mt = 0; mt < 2; mt++)
        #pragma unroll
        for (int nt = 0; nt < 8; nt++)
            #pragma unroll
            for (int i = 0; i < 4; i++) acc[mt][nt][i] = 0.0f;

    for (int k0 = 0; k0 < K; k0 += 32) {
        // ---- load A tile: 128 rows x 32 k ----
        #pragma unroll
        for (int i = 0; i < 4; i++) {
            int fi  = tid + i * 256;       // float4 index 0..1023
            int row = fi >> 3;             // 0..127
            int c4  = fi & 7;              // 0..7
            float4 v = make_float4(0.f, 0.f, 0.f, 0.f);
            if (m0 + row < M)
                v = *(const float4*)(A + (size_t)(m0 + row) * K + k0 + c4 * 4);
            uint32_t* p = &As[row * AS_STRIDE + c4 * 4];
            p[0] = f2tf32(v.x); p[1] = f2tf32(v.y);
            p[2] = f2tf32(v.z); p[3] = f2tf32(v.w);
        }
        // ---- load B tile: 32 k x 128 n ----
        #pragma unroll
        for (int i = 0; i < 4; i++) {
            int fi  = tid + i * 256;
            int row = fi >> 5;             // 0..31
            int c4  = fi & 31;             // 0..31
            float4 v = *(const float4*)(B + (size_t)(k0 + row) * HD + c4 * 4);
            uint32_t* p = &Bs[row * BS_STRIDE + c4 * 4];
            p[0] = f2tf32(v.x); p[1] = f2tf32(v.y);
            p[2] = f2tf32(v.z); p[3] = f2tf32(v.w);
        }
        __syncthreads();

        #pragma unroll
        for (int kk = 0; kk < 32; kk += 8) {
            uint32_t af[2][4];
            #pragma unroll
            for (int mt = 0; mt < 2; mt++) {
                int rbase = warp_m * 32 + mt * 16;
                af[mt][0] = As[(rbase + gid)     * AS_STRIDE + kk + tig];
                af[mt][1] = As[(rbase + gid + 8) * AS_STRIDE + kk + tig];
                af[mt][2] = As[(rbase + gid)     * AS_STRIDE + kk + tig + 4];
                af[mt][3] = As[(rbase + gid + 8) * AS_STRIDE + kk + tig + 4];
            }
            uint32_t bf[8][2];
            #pragma unroll
            for (int nt = 0; nt < 8; nt++) {
                int nbase = warp_n * 64 + nt * 8;
                bf[nt][0] = Bs[(kk + tig)     * BS_STRIDE + nbase + gid];
                bf[nt][1] = Bs[(kk + tig + 4) * BS_STRIDE + nbase + gid];
            }
            #pragma unroll
            for (int mt = 0; mt < 2; mt++)
                #pragma unroll
                for (int nt = 0; nt < 8; nt++)
                    mma_tf32(acc[mt][nt], af[mt][0], af[mt][1], af[mt][2], af[mt][3],
                             bf[nt][0], bf[nt][1]);
        }
        __syncthreads();
    }

    // ---- epilogue: bias + optional relu; fp32 or bf16 stores ----
    #pragma unroll
    for (int mt = 0; mt < 2; mt++) {
        #pragma unroll
        for (int half = 0; half < 2; half++) {
            int m = m0 + warp_m * 32 + mt * 16 + gid + half * 8;
            if (m < M) {
                #pragma unroll
                for (int nt = 0; nt < 8; nt++) {
                    int col = warp_n * 64 + nt * 8 + tig * 2;   // even
                    float v0 = acc[mt][nt][half * 2 + 0];
                    float v1 = acc[mt][nt][half * 2 + 1];
                    if (bias) {
                        v0 += __ldg(&bias[col]);
                        v1 += __ldg(&bias[col + 1]);
                    }
                    if (RELU_OUT) { v0 = fmaxf(v0, 0.f); v1 = fmaxf(v1, 0.f); }
                    if (BF16_OUT) {
                        Cbf[(size_t)m * 64 + (col >> 1)] = __floats2bfloat162_rn(v0, v1);
                    } else {
                        *(float2*)(C + (size_t)m * HD + col) = make_float2(v0, v1);
                    }
                }
            }
        }
    }
}

// ---------------------------------------------------------
// CSR aggregation over bf16 features: one warp per dst node, fp32 accumulate.
// out[i] = [relu]( bias + dis[i]^2 * xw[i] + sum_j coef_j * xw[src_j] )
// xwbf rows: 64 x __nv_bfloat162 (256B); lane handles features [lane*4, lane*4+4)
// ---------------------------------------------------------
__device__ __forceinline__ float4 ld_bf4(const __nv_bfloat162* __restrict__ base,
                                         int row, int lane) {
    uint2 u = __ldg((const uint2*)(base + (size_t)row * 64 + lane * 2));
    __nv_bfloat162 p0 = *reinterpret_cast<__nv_bfloat162*>(&u.x);
    __nv_bfloat162 p1 = *reinterpret_cast<__nv_bfloat162*>(&u.y);
    float2 f0 = __bfloat1622float2(p0);
    float2 f1 = __bfloat1622float2(p1);
    return make_float4(f0.x, f0.y, f1.x, f1.y);
}

template <bool RELU>
__global__ void agg_kernel(const __nv_bfloat162* __restrict__ xwbf,
                           const float* __restrict__ bias,
                           float* __restrict__ out, int n)
{
    int g    = blockIdx.x * blockDim.x + threadIdx.x;
    int node = g >> 5;
    int lane = g & 31;
    if (node >= n) return;

    int start = g_rowstart[node];
    int deg   = g_cnt[node];
    float ds  = g_dis[node];
    float c   = ds * ds;

    float4 b = ((const float4*)bias)[lane];
    float4 v = ld_bf4(xwbf, node, lane);
    float4 acc = make_float4(fmaf(v.x, c, b.x), fmaf(v.y, c, b.y),
                             fmaf(v.z, c, b.z), fmaf(v.w, c, b.w));

    const int2* ep = g_epack + start;
    int j = 0;
    for (; j + 4 <= deg; j += 4) {
        int2 e0 = __ldg(ep + j);
        int2 e1 = __ldg(ep + j + 1);
        int2 e2 = __ldg(ep + j + 2);
        int2 e3 = __ldg(ep + j + 3);
        float4 u0 = ld_bf4(xwbf, e0.x, lane);
        float4 u1 = ld_bf4(xwbf, e1.x, lane);
        float4 u2 = ld_bf4(xwbf, e2.x, lane);
        float4 u3 = ld_bf4(xwbf, e3.x, lane);
        float w0 = __int_as_float(e0.y), w1 = __int_as_float(e1.y);
        float w2 = __int_as_float(e2.y), w3 = __int_as_float(e3.y);
        acc.x = fmaf(u0.x, w0, acc.x); acc.y = fmaf(u0.y, w0, acc.y);
        acc.z = fmaf(u0.z, w0, acc.z); acc.w = fmaf(u0.w, w0, acc.w);
        acc.x = fmaf(u1.x, w1, acc.x); acc.y = fmaf(u1.y, w1, acc.y);
        acc.z = fmaf(u1.z, w1, acc.z); acc.w = fmaf(u1.w, w1, acc.w);
        acc.x = fmaf(u2.x, w2, acc.x); acc.y = fmaf(u2.y, w2, acc.y);
        acc.z = fmaf(u2.z, w2, acc.z); acc.w = fmaf(u2.w, w2, acc.w);
        acc.x = fmaf(u3.x, w3, acc.x); acc.y = fmaf(u3.y, w3, acc.y);
        acc.z = fmaf(u3.z, w3, acc.z); acc.w = fmaf(u3.w, w3, acc.w);
    }
    for (; j < deg; j++) {
        int2 e0 = __ldg(ep + j);
        float4 u0 = ld_bf4(xwbf, e0.x, lane);
        float w0 = __int_as_float(e0.y);
        acc.x = fmaf(u0.x, w0, acc.x); acc.y = fmaf(u0.y, w0, acc.y);
        acc.z = fmaf(u0.z, w0, acc.z); acc.w = fmaf(u0.w, w0, acc.w);
    }

    if (RELU) {
        acc.x = fmaxf(acc.x, 0.f); acc.y = fmaxf(acc.y, 0.f);
        acc.z = fmaxf(acc.z, 0.f); acc.w = fmaxf(acc.w, 0.f);
    }
    *((float4*)(out + (size_t)node * HD) + lane) = acc;
}

// ---------------------------------------------------------
// edge score: sigmoid( relu(A[s]+B[d]) . w2 + b2 )   (one warp per edge, bf16 A/B)
// ---------------------------------------------------------
__global__ void edge_score_kernel(const __nv_bfloat162* __restrict__ Af,
                                  const __nv_bfloat162* __restrict__ Bf,
                                  const float* __restrict__ w2,
                                  const float* __restrict__ b2,
                                  float* __restrict__ out, int E)
{
    int g    = blockIdx.x * blockDim.x + threadIdx.x;
    int e    = g >> 5;
    int lane = g & 31;
    if (e >= E) return;
    int2 sd = g_sd[e];
    float4 a = ld_bf4(Af, sd.x, lane);
    float4 b = ld_bf4(Bf, sd.y, lane);
    float4 w = *((const float4*)w2 + lane);
    float sum = fmaxf(a.x + b.x, 0.f) * w.x
              + fmaxf(a.y + b.y, 0.f) * w.y
              + fmaxf(a.z + b.z, 0.f) * w.z
              + fmaxf(a.w + b.w, 0.f) * w.w;
    #pragma unroll
    for (int o = 16; o; o >>= 1) sum += __shfl_xor_sync(0xffffffffu, sum, o);
    if (lane == 0) {
        float z = sum + b2[0];
        out[e] = 1.0f / (1.0f + __expf(-z));
    }
}

// ---------------------------------------------------------
// host side
// ---------------------------------------------------------
static void gemm_f32(const float* A, const float* B, const float* bias, float* C,
                     int M, int K, bool relu_out)
{
    dim3 grid((M + 127) / 128);
    if (relu_out) tgemm_kernel<true,  false><<<grid, 256>>>(A, B, bias, C, nullptr, M, K);
    else          tgemm_kernel<false, false><<<grid, 256>>>(A, B, bias, C, nullptr, M, K);
}

static void gemm_bf16(const float* A, const float* B, const float* bias,
                      __nv_bfloat162* Cbf, int M, int K)
{
    dim3 grid((M + 127) / 128);
    tgemm_kernel<false, true><<<grid, 256>>>(A, B, bias, nullptr, Cbf, M, K);
}

extern "C" void kernel_launch(void* const* d_in, const int* in_sizes, int n_in,
                              void* d_out, int out_size)
{
    const float* nf      = (const float*)d_in[0];
    const void*  ei      = d_in[1];
    const float* enc_w1  = (const float*)d_in[2];
    const float* enc_b1  = (const float*)d_in[3];
    const float* enc_w2  = (const float*)d_in[4];
    const float* enc_b2  = (const float*)d_in[5];
    const float* conv_w[3] = {(const float*)d_in[6], (const float*)d_in[8], (const float*)d_in[10]};
    const float* conv_b[3] = {(const float*)d_in[7], (const float*)d_in[9], (const float*)d_in[11]};
    const float* cls_w1  = (const float*)d_in[12];
    const float* cls_b1  = (const float*)d_in[13];
    const float* cls_w2  = (const float*)d_in[14];
    const float* cls_b2  = (const float*)d_in[15];

    int K1 = in_sizes[2] / HD;        // encoder input dim (256)
    int N  = in_sizes[0] / K1;        // nodes
    int E  = in_sizes[1] / 2;         // edges

    float *px, *pxw, *pacc;
    __nv_bfloat162 *pbf1, *pbf2;
    cudaGetSymbolAddress((void**)&px,   g_x);
    cudaGetSymbolAddress((void**)&pxw,  g_xw);
    cudaGetSymbolAddress((void**)&pacc, g_acc);
    cudaGetSymbolAddress((void**)&pbf1, g_bf1);
    cudaGetSymbolAddress((void**)&pbf2, g_bf2);

    int nblk  = (N + 255) / 256;
    int eblk  = (E + 255) / 256;
    int wblk  = (int)(((long)N * 32 + 255) / 256);   // warp-per-node grids
    int ewblk = (int)(((long)E * 32 + 255) / 256);   // warp-per-edge grids

    // ---- prep: edge decode, degrees, CSR build ----
    detect_kernel<<<1, 32>>>((const int*)ei);
    zero_cnt_kernel<<<nblk, 256>>>(N);
    prep_edges_kernel<<<eblk, 256>>>(ei, E);
    dis_kernel<<<nblk, 256>>>(N);
    scan1_kernel<<<nblk, 256>>>(N);
    scan2_kernel<<<1, 256>>>(nblk);
    scan3_kernel<<<nblk, 256>>>(N);
    fill_kernel<<<eblk, 256>>>(E);

    // ---- node encoder: x = relu(nf@w1+b1) @ w2 + b2 ----
    gemm_f32(nf,  enc_w1, enc_b1, pxw, N, K1, true);
    gemm_f32(pxw, enc_w2, enc_b2, px,  N, HD, false);

    // ---- 3 GCN layers: GEMM (bf16 out) then CSR aggregate (bias+self+relu fused)
    const float* cur = px;
    for (int l = 0; l < 3; l++) {
        gemm_bf16(cur, conv_w[l], nullptr, pbf1, N, HD);
        if (l < 2) agg_kernel<true ><<<wblk, 256>>>(pbf1, conv_b[l], pacc, N);
        else       agg_kernel<false><<<wblk, 256>>>(pbf1, conv_b[l], pacc, N);
        cur = pacc;
    }

    // ---- classifier factorization: A = x3@W1_top + b1, B = x3@W1_bot (bf16) ----
    gemm_bf16(pacc, cls_w1,           cls_b1,  pbf1, N, HD);
    gemm_bf16(pacc, cls_w1 + HD * HD, nullptr, pbf2, N, HD);

    edge_score_kernel<<<ewblk, 256>>>(pbf1, pbf2, cls_w2, cls_b2, (float*)d_out, E);
}